// round 8
// baseline (speedup 1.0000x reference)
#include <cuda_runtime.h>
#include <cuda_fp16.h>
#include <cstdint>

#define NUM_EMB 16384
#define BT      16384
#define D       64
#define N_TILE  128
#define NTILES  (NUM_EMB / N_TILE)     // 128
#define M_TILE  128
#define NCTA    (BT / M_TILE)          // 128
#define CAP     256
#define EPSI    1000                   // capture window, int dot domain (~13.7 sigma)

// smem layout (dynamic): A 8KB | B0 8KB | B1 8KB | cand 64KB
#define SM_A    0
#define SM_B0   8192
#define SM_B1   16384
#define SM_CAND 24576
#define SM_TOT  90112

// ---------------- device scratch ----------------
__device__ float    g_qcb[NUM_EMB * D];     // projected codebook fp32 (gather)
__device__ float    g_cn [NUM_EMB * D];     // normalized codebook fp32 (exact rescore)
__device__ __half   g_cbh[NUM_EMB * D];     // normalized codebook fp16 (refine)
__device__ uint32_t g_cbi[NUM_EMB * 16];    // normalized codebook s8 packed (screen)
__device__ int      g_idx[BT];
__device__ float    g_partials[128];
__device__ int      g_done;                 // zero-init; reset by last kCD block

// ---------------- helpers ----------------
__device__ __forceinline__ uint32_t smem_u32(const void* p) {
    uint32_t a;
    asm("{ .reg .u64 t; cvta.to.shared.u64 t, %1; cvt.u32.u64 %0, t; }" : "=r"(a) : "l"(p));
    return a;
}
// 16B-chunk XOR swizzle for 64B rows: chunk' = chunk ^ ((row>>1)&3)
__device__ __forceinline__ uint32_t swz4(uint32_t chunk, uint32_t row) {
    return chunk ^ ((row >> 1) & 3u);
}

#define LDSM_X4(r0, r1, r2, r3, addr) \
    asm volatile("ldmatrix.sync.aligned.m8n8.x4.shared.b16 {%0,%1,%2,%3}, [%4];" \
                 : "=r"(r0), "=r"(r1), "=r"(r2), "=r"(r3) : "r"(addr))

#define IMMA16832(c0, c1, c2, c3, a0, a1, a2, a3, b0, b1) \
    asm volatile("mma.sync.aligned.m16n8k32.row.col.s32.s8.s8.s32 " \
                 "{%0,%1,%2,%3}, {%4,%5,%6,%7}, {%8,%9}, {%0,%1,%2,%3};" \
                 : "+r"(c0), "+r"(c1), "+r"(c2), "+r"(c3) \
                 : "r"(a0), "r"(a1), "r"(a2), "r"(a3), "r"(b0), "r"(b1))

#define CP_ASYNC16(dst, src) \
    asm volatile("cp.async.cg.shared.global [%0], [%1], 16;" :: "r"(dst), "l"(src) : "memory")
#define CP_COMMIT()  asm volatile("cp.async.commit_group;" ::: "memory")
#define CP_WAIT1()   asm volatile("cp.async.wait_group 1;" ::: "memory")
#define CP_WAIT0()   asm volatile("cp.async.wait_group 0;" ::: "memory")

__device__ __forceinline__ uint32_t pack4s8(float a, float b, float c, float d) {
    int q0 = __float2int_rn(a), q1 = __float2int_rn(b);
    int q2 = __float2int_rn(c), q3 = __float2int_rn(d);
    return (uint32_t)(q0 & 255) | ((uint32_t)(q1 & 255) << 8) |
           ((uint32_t)(q2 & 255) << 16) | ((uint32_t)(q3 & 255) << 24);
}

// ================= kPrep: project + normalize; fp32 + fp16 + s8 codebooks =====
__global__ void __launch_bounds__(256) kPrep(const float* __restrict__ cb,
                                             const float* __restrict__ pw,
                                             const float* __restrict__ pb) {
    __shared__ float pwT[64 * 64];
    __shared__ float qs [64 * 64];
    __shared__ float rnorm[64];
    const int tid = threadIdx.x;

    for (int i = tid; i < 4096; i += 256) {
        int c = i >> 6, k = i & 63;
        pwT[k * 64 + c] = pw[i];
    }
    __syncthreads();

    const int c  = tid & 63;
    const int rg = tid >> 6;
    const float bias = pb[c];
    for (int rr = 0; rr < 16; rr++) {
        int lrow = rg * 16 + rr;
        int row  = blockIdx.x * 64 + lrow;
        const float* cbr = cb + row * 64;
        float acc = bias;
#pragma unroll
        for (int k = 0; k < 64; k++)
            acc = fmaf(__ldg(cbr + k), pwT[k * 64 + c], acc);
        qs[lrow * 64 + c] = acc;
    }
    __syncthreads();

    if (tid < 64) {
        float s = 0.f;
#pragma unroll
        for (int k = 0; k < 64; k++) {
            float v = qs[tid * 64 + k];
            s = fmaf(v, v, s);
        }
        rnorm[tid] = 1.0f / fmaxf(sqrtf(s), 1e-12f);
    }
    __syncthreads();

    const int base = blockIdx.x * 4096;
    for (int i = tid; i < 4096; i += 256) {
        float v = qs[i];
        int row = i >> 6;
        g_qcb[base + i] = v;
        float cn = v * rnorm[row];
        g_cn [base + i] = cn;
        g_cbh[base + i] = __float2half_rn(cn);
    }
    // s8 packed codebook
    for (int i = tid; i < 1024; i += 256) {
        int row = i >> 4;
        int j4  = i & 15;
        const float* qr = qs + row * 64 + j4 * 4;
        float rn = rnorm[row] * 127.0f;
        g_cbi[(size_t)(blockIdx.x * 64 + row) * 16 + j4] =
            pack4s8(qr[0] * rn, qr[1] * rn, qr[2] * rn, qr[3] * rn);
    }
}

// ================= kMain: int8 IMMA screen + capture + fused rescore =================
__global__ void __launch_bounds__(256, 1) kMain(const float* __restrict__ z,
                                                float* __restrict__ out, int out_size) {
    extern __shared__ char smem[];
    __shared__ int s_cnt[128];
    const uint32_t sb = smem_u32(smem);
    unsigned short* s_cand = (unsigned short*)(smem + SM_CAND);
    const int tid  = threadIdx.x;
    const int lane = tid & 31;
    const int w    = tid >> 5;
    const int tokbase = blockIdx.x * M_TILE;

    if (tid < 128) s_cnt[tid] = 0;

    // ---- token prep: normalize, quantize s8, swizzled smem A (64B rows) ----
    if (tid < 128) {
        const int token = tokbase + tid;
        const float4* z4 = (const float4*)(z + (size_t)token * D);
        float v[64];
        float s = 0.f;
#pragma unroll
        for (int j = 0; j < 16; j++) {
            float4 t = z4[j];
            v[4 * j] = t.x; v[4 * j + 1] = t.y; v[4 * j + 2] = t.z; v[4 * j + 3] = t.w;
            s += t.x * t.x + t.y * t.y + t.z * t.z + t.w * t.w;
        }
        const float inv = 127.0f / fmaxf(sqrtf(s), 1e-12f);
        const uint32_t rowbase = (uint32_t)tid * 64u;
#pragma unroll
        for (int j = 0; j < 16; j++) {
            uint32_t pk = pack4s8(v[4*j] * inv, v[4*j+1] * inv, v[4*j+2] * inv, v[4*j+3] * inv);
            uint32_t addr = rowbase + (swz4((uint32_t)(j >> 2), (uint32_t)tid) << 4) + (uint32_t)(j & 3) * 4u;
            *(uint32_t*)(smem + SM_A + addr) = pk;
        }
    }

#define FILL(stage, tile_)                                                        \
    do {                                                                          \
        _Pragma("unroll")                                                         \
        for (int i = 0; i < 2; i++) {                                             \
            int idx = tid + i * 256;                                              \
            uint32_t code = (uint32_t)idx >> 2;                                   \
            uint32_t ch   = (uint32_t)idx & 3u;                                   \
            uint32_t dst  = sb + (stage) + code * 64u + (swz4(ch, code) << 4);    \
            const char* src = (const char*)g_cbi + (size_t)(tile_) * 8192 + code * 64 + ch * 16; \
            CP_ASYNC16(dst, src);                                                 \
        }                                                                         \
        CP_COMMIT();                                                              \
    } while (0)

    FILL(SM_B0, 0);
    FILL(SM_B1, 1);
    __syncthreads();

    // ---- A fragments (persistent, 8 regs) ----
    uint32_t a[8];
    {
        const uint32_t row_l = (uint32_t)((lane & 7) | (((lane >> 3) & 1) << 3));
        const uint32_t arow  = (uint32_t)(w * 16) + row_l;
        const uint32_t cb0   = (uint32_t)(lane >> 4);
        uint32_t base = sb + SM_A + arow * 64u;
        LDSM_X4(a[0], a[1], a[2], a[3], base + (swz4(cb0,      arow) << 4));
        LDSM_X4(a[4], a[5], a[6], a[7], base + (swz4(2u + cb0, arow) << 4));
    }

    int best0 = -1000000000, best1 = -1000000000;
    const int tl0 = w * 16 + (lane >> 2);
    const int tl1 = tl0 + 8;

    for (int t = 0; t < NTILES; t++) {
        if (t + 1 < NTILES) { CP_WAIT1(); } else { CP_WAIT0(); }
        __syncthreads();
        const uint32_t Bb = sb + ((t & 1) ? SM_B1 : SM_B0);

#pragma unroll 1
        for (int nb = 0; nb < 16; nb += 2) {
            uint32_t bb[2][4];
#pragma unroll
            for (int u = 0; u < 2; u++) {
                const uint32_t crow = (uint32_t)((nb + u) * 8) + (uint32_t)(lane & 7);
                LDSM_X4(bb[u][0], bb[u][1], bb[u][2], bb[u][3],
                        Bb + crow * 64u + (swz4((uint32_t)(lane >> 3), crow) << 4));
            }

            int c0[4] = {0, 0, 0, 0}, c1[4] = {0, 0, 0, 0};
            IMMA16832(c0[0], c0[1], c0[2], c0[3], a[0], a[1], a[2], a[3], bb[0][0], bb[0][1]);
            IMMA16832(c0[0], c0[1], c0[2], c0[3], a[4], a[5], a[6], a[7], bb[0][2], bb[0][3]);
            IMMA16832(c1[0], c1[1], c1[2], c1[3], a[0], a[1], a[2], a[3], bb[1][0], bb[1][1]);
            IMMA16832(c1[0], c1[1], c1[2], c1[3], a[4], a[5], a[6], a[7], bb[1][2], bb[1][3]);

            const int thr0 = best0 - EPSI;
            const int thr1 = best1 - EPSI;
            const int m0 = max(max(c0[0], c0[1]), max(c1[0], c1[1]));
            const int m1 = max(max(c0[2], c0[3]), max(c1[2], c1[3]));
            const bool p = (m0 >= thr0) | (m1 >= thr1);
            const unsigned bal = __ballot_sync(0xFFFFFFFFu, p);
            if (bal) {   // uniform branch, rare
                const int cbase = t * N_TILE + nb * 8 + 2 * (lane & 3);
                if (c0[0] >= thr0) { int q = atomicAdd(&s_cnt[tl0], 1); s_cand[tl0 * CAP + (q & (CAP-1))] = (unsigned short)cbase; }
                if (c0[1] >= thr0) { int q = atomicAdd(&s_cnt[tl0], 1); s_cand[tl0 * CAP + (q & (CAP-1))] = (unsigned short)(cbase + 1); }
                if (c0[2] >= thr1) { int q = atomicAdd(&s_cnt[tl1], 1); s_cand[tl1 * CAP + (q & (CAP-1))] = (unsigned short)cbase; }
                if (c0[3] >= thr1) { int q = atomicAdd(&s_cnt[tl1], 1); s_cand[tl1 * CAP + (q & (CAP-1))] = (unsigned short)(cbase + 1); }
                if (c1[0] >= thr0) { int q = atomicAdd(&s_cnt[tl0], 1); s_cand[tl0 * CAP + (q & (CAP-1))] = (unsigned short)(cbase + 8); }
                if (c1[1] >= thr0) { int q = atomicAdd(&s_cnt[tl0], 1); s_cand[tl0 * CAP + (q & (CAP-1))] = (unsigned short)(cbase + 9); }
                if (c1[2] >= thr1) { int q = atomicAdd(&s_cnt[tl1], 1); s_cand[tl1 * CAP + (q & (CAP-1))] = (unsigned short)(cbase + 8); }
                if (c1[3] >= thr1) { int q = atomicAdd(&s_cnt[tl1], 1); s_cand[tl1 * CAP + (q & (CAP-1))] = (unsigned short)(cbase + 9); }
            }
            best0 = max(best0, m0);
            best1 = max(best1, m1);
        }
        // merge lane-local bests across the quad (tightens capture threshold)
        best0 = max(best0, __shfl_xor_sync(0xFFFFFFFFu, best0, 1));
        best0 = max(best0, __shfl_xor_sync(0xFFFFFFFFu, best0, 2));
        best1 = max(best1, __shfl_xor_sync(0xFFFFFFFFu, best1, 1));
        best1 = max(best1, __shfl_xor_sync(0xFFFFFFFFu, best1, 2));

        __syncthreads();
        if (t + 2 < NTILES) FILL(((t & 1) ? SM_B1 : SM_B0), t + 2);
    }
#undef FILL

    // ================= fused rescore: refine (fp16) then exact (fp32) =================
    __syncthreads();   // B stages dead; reuse as scratch
    float* s_z  = (float*)(smem + SM_B0) + w * 64;     // this warp's z row (8*64*4 = 2KB)
    float* s_rv = (float*)(smem + SM_B1) + w * 256;    // refined values (8*256*4 = 8KB)

    for (int i = 0; i < 16; i++) {
        const int r = w * 16 + i;
        const int tok = tokbase + r;
        float ps = 0.f;
        if (lane < 16) {
            float4 vz = ((const float4*)(z + (size_t)tok * D))[lane];
            ((float4*)s_z)[lane] = vz;
            ps = vz.x * vz.x + vz.y * vz.y + vz.z * vz.z + vz.w * vz.w;
        }
#pragma unroll
        for (int off = 16; off; off >>= 1) ps += __shfl_xor_sync(0xFFFFFFFFu, ps, off);
        const float nrm = sqrtf(ps);
        __syncwarp();

        int cnt = s_cnt[r]; if (cnt > CAP) cnt = CAP;
        float rmax = -1e30f;
        for (int basec = 0; basec < cnt; basec += 32) {
            const int ci = basec + lane;
            float val = -1e30f;
            if (ci < cnt) {
                const int code = s_cand[r * CAP + ci];
                const uint4* ch4 = (const uint4*)(g_cbh + (size_t)code * D);  // 8 x uint4 per row
                float acc = 0.f;
#pragma unroll
                for (int qq = 0; qq < 8; qq++) {
                    uint4 uu = __ldg(&ch4[qq]);
                    const __half2* h2 = (const __half2*)&uu;                   // 4 half2
#pragma unroll
                    for (int e = 0; e < 4; e++) {
                        float2 f2 = __half22float2(h2[e]);
                        acc = fmaf(s_z[qq * 8 + 2 * e],     f2.x, acc);
                        acc = fmaf(s_z[qq * 8 + 2 * e + 1], f2.y, acc);
                    }
                }
                val = acc;
                s_rv[ci] = val;
            }
            rmax = fmaxf(rmax, val);
        }
#pragma unroll
        for (int off = 16; off; off >>= 1) rmax = fmaxf(rmax, __shfl_xor_sync(0xFFFFFFFFu, rmax, off));
        const float thr2 = rmax - 1.5e-3f * nrm;
        __syncwarp();

        float bv = -1e30f;
        int   bi = 0x7fffffff;
        for (int basec = 0; basec < cnt; basec += 32) {
            const int ci = basec + lane;
            if (ci < cnt && s_rv[ci] >= thr2) {
                const int code = s_cand[r * CAP + ci];
                const float4* cr = (const float4*)(g_cn + (size_t)code * D);
                float d0 = 0.f, d1 = 0.f, d2 = 0.f, d3 = 0.f;
#pragma unroll
                for (int j = 0; j < 16; j++) {
                    float4 b = __ldg(&cr[j]);
                    float4 aa = ((const float4*)s_z)[j];
                    d0 = fmaf(aa.x, b.x, d0);
                    d1 = fmaf(aa.y, b.y, d1);
                    d2 = fmaf(aa.z, b.z, d2);
                    d3 = fmaf(aa.w, b.w, d3);
                }
                float d = (d0 + d1) + (d2 + d3);
                if (d > bv || (d == bv && code < bi)) { bv = d; bi = code; }
            }
        }
#pragma unroll
        for (int off = 16; off; off >>= 1) {
            float ov = __shfl_xor_sync(0xFFFFFFFFu, bv, off);
            int   oi = __shfl_xor_sync(0xFFFFFFFFu, bi, off);
            if (ov > bv || (ov == bv && oi < bi)) { bv = ov; bi = oi; }
        }
        if (lane == 0) {
            g_idx[tok] = bi;
            const int off = BT * D + 1 + tok;
            if (off < out_size) out[off] = (float)bi;
        }
        __syncwarp();
    }
}

// ================= kCD: gather quantized + MSE + finalize loss =================
__global__ void __launch_bounds__(256) kCD(const float* __restrict__ z,
                                           float* __restrict__ out, int out_size) {
    __shared__ float red[256];
    __shared__ int s_last;
    const int tid = threadIdx.x;
    const float4* z4 = (const float4*)z;
    const float4* q4 = (const float4*)g_qcb;
    float4* o4 = (float4*)out;

    float ps = 0.f;
#pragma unroll
    for (int i = 0; i < 8; i++) {
        int g = blockIdx.x * 2048 + i * 256 + tid;
        int token = g >> 4;
        int idx = g_idx[token];
        float4 q = q4[idx * 16 + (g & 15)];
        float4 zz = z4[g];
        if (g * 4 + 3 < out_size) o4[g] = q;
        float dx = q.x - zz.x, dy = q.y - zz.y;
        float dz_ = q.z - zz.z, dw = q.w - zz.w;
        ps += dx * dx + dy * dy + dz_ * dz_ + dw * dw;
    }
    red[tid] = ps;
    __syncthreads();
    for (int st = 128; st > 0; st >>= 1) {
        if (tid < st) red[tid] += red[tid + st];
        __syncthreads();
    }
    if (tid == 0) {
        g_partials[blockIdx.x] = red[0];
        __threadfence();
        int prev = atomicAdd(&g_done, 1);
        s_last = (prev == 127);
    }
    __syncthreads();
    if (s_last) {
        __threadfence();
        if (tid < 128) red[tid] = g_partials[tid];
        __syncthreads();
        for (int st = 64; st > 0; st >>= 1) {
            if (tid < st) red[tid] += red[tid + st];
            __syncthreads();
        }
        if (tid == 0) {
            float loss = 1.25f * red[0] / (float)(BT * D);
            if (BT * D < out_size) out[BT * D] = loss;
            g_done = 0;   // reset for next graph replay
        }
    }
}

// ================= launch =================
extern "C" void kernel_launch(void* const* d_in, const int* in_sizes, int n_in,
                              void* d_out, int out_size) {
    const float* z  = (const float*)d_in[0];
    const float* cb = (const float*)d_in[1];
    const float* pw = (const float*)d_in[2];
    const float* pb = (const float*)d_in[3];
    // d_in[4] = scale: positive constant, cannot change argmin or any output value.
    float* out = (float*)d_out;

    cudaFuncSetAttribute(kMain, cudaFuncAttributeMaxDynamicSharedMemorySize, SM_TOT);

    kPrep<<<NUM_EMB / 64, 256>>>(cb, pw, pb);
    kMain<<<NCTA, 256, SM_TOT>>>(z, out, out_size);
    kCD<<<128, 256>>>(z, out, out_size);
}